// round 3
// baseline (speedup 1.0000x reference)
#include <cuda_runtime.h>
#include <cuda_bf16.h>
#include <cstddef>

#define N_USERS 100000
#define N_ITEMS 50000
#define N_TOT   150000
#define EMB_D   64
#define NNZ     4800000
#define CAP     128            // slot capacity per row (Poisson mean 32; P(overflow) ~ 1e-18)
#define CAPSH   7

// ---- device-global scratch (no runtime allocation allowed) ----
// bf16 layer activations: 64 bf16 per row = 32 x bf162 (128 B/row)
__device__ __align__(256) __nv_bfloat162 g_x0h[(size_t)N_TOT * 32];
__device__ __align__(256) __nv_bfloat162 g_b1h[(size_t)N_TOT * 32];
__device__ __align__(256) __nv_bfloat162 g_b2h[(size_t)N_TOT * 32];
__device__ __align__(256) int2 g_slots[(size_t)N_TOT * CAP];   // (col, val_bits)
__device__ int g_cnt[N_TOT];

// -------- fp32 inputs -> contiguous bf16 x0 (layer-0 activation) --------
__global__ __launch_bounds__(256) void convert_kernel(
    const float4* __restrict__ u, const float4* __restrict__ it)
{
    int i = blockIdx.x * blockDim.x + threadIdx.x;   // float4 index
    if (i >= N_TOT * 16) return;
    float4 v = (i < N_USERS * 16) ? u[i] : it[i - N_USERS * 16];
    __nv_bfloat162 lo = __floats2bfloat162_rn(v.x, v.y);
    __nv_bfloat162 hi = __floats2bfloat162_rn(v.z, v.w);
    uint2 packed;
    packed.x = *reinterpret_cast<unsigned*>(&lo);
    packed.y = *reinterpret_cast<unsigned*>(&hi);
    *reinterpret_cast<uint2*>(&g_x0h[2 * i]) = packed;
}

// -------- one-pass slot scatter (no scan): 4 edges/thread, vectorized loads --------
__global__ __launch_bounds__(256) void scatter_kernel(
    const int4* __restrict__ rows4, const int4* __restrict__ cols4,
    const float4* __restrict__ vals4, int base4, int n4)
{
    int i = blockIdx.x * blockDim.x + threadIdx.x;
    if (i >= n4) return;
    i += base4;
    int4   r = rows4[i];
    int4   c = cols4[i];
    float4 v = vals4[i];
    int p;
    p = atomicAdd(&g_cnt[r.x], 1);
    if (p < CAP) g_slots[((size_t)r.x << CAPSH) + p] = make_int2(c.x, __float_as_int(v.x));
    p = atomicAdd(&g_cnt[r.y], 1);
    if (p < CAP) g_slots[((size_t)r.y << CAPSH) + p] = make_int2(c.y, __float_as_int(v.y));
    p = atomicAdd(&g_cnt[r.z], 1);
    if (p < CAP) g_slots[((size_t)r.z << CAPSH) + p] = make_int2(c.z, __float_as_int(v.z));
    p = atomicAdd(&g_cnt[r.w], 1);
    if (p < CAP) g_slots[((size_t)r.w << CAPSH) + p] = make_int2(c.w, __float_as_int(v.w));
}

// -------- SpMM, bf16 in -> bf16 out, fp32 accumulate, warp per row --------
__global__ __launch_bounds__(256) void spmm_h_kernel(
    const __nv_bfloat162* __restrict__ x, __nv_bfloat162* __restrict__ out)
{
    int w    = (blockIdx.x * blockDim.x + threadIdx.x) >> 5;
    int lane = threadIdx.x & 31;
    if (w >= N_TOT) return;

    int deg = g_cnt[w];
    if (deg > CAP) deg = CAP;
    const int2* es = g_slots + ((size_t)w << CAPSH);

    float ax = 0.0f, ay = 0.0f;
    int j = 0;
    for (; j + 4 <= deg; j += 4) {
        int2 e0 = es[j], e1 = es[j + 1], e2 = es[j + 2], e3 = es[j + 3];
        __nv_bfloat162 v0 = x[e0.x * 32 + lane];
        __nv_bfloat162 v1 = x[e1.x * 32 + lane];
        __nv_bfloat162 v2 = x[e2.x * 32 + lane];
        __nv_bfloat162 v3 = x[e3.x * 32 + lane];
        float s0 = __int_as_float(e0.y), s1 = __int_as_float(e1.y);
        float s2 = __int_as_float(e2.y), s3 = __int_as_float(e3.y);
        ax += s0 * __low2float(v0)  + s1 * __low2float(v1)
            + s2 * __low2float(v2)  + s3 * __low2float(v3);
        ay += s0 * __high2float(v0) + s1 * __high2float(v1)
            + s2 * __high2float(v2) + s3 * __high2float(v3);
    }
    for (; j < deg; ++j) {
        int2 e = es[j];
        __nv_bfloat162 v = x[e.x * 32 + lane];
        float s = __int_as_float(e.y);
        ax += s * __low2float(v);
        ay += s * __high2float(v);
    }
    out[w * 32 + lane] = __floats2bfloat162_rn(ax, ay);
}

// -------- layer 3 + fused mean epilogue: out = 0.25*(x0 + b1 + b2 + A*b2) --------
__global__ __launch_bounds__(256) void spmm_final_kernel(
    const float* __restrict__ u, const float* __restrict__ it,
    float* __restrict__ out)
{
    int w    = (blockIdx.x * blockDim.x + threadIdx.x) >> 5;
    int lane = threadIdx.x & 31;
    if (w >= N_TOT) return;

    int deg = g_cnt[w];
    if (deg > CAP) deg = CAP;
    const int2* es = g_slots + ((size_t)w << CAPSH);

    float ax = 0.0f, ay = 0.0f;
    int j = 0;
    for (; j + 4 <= deg; j += 4) {
        int2 e0 = es[j], e1 = es[j + 1], e2 = es[j + 2], e3 = es[j + 3];
        __nv_bfloat162 v0 = g_b2h[e0.x * 32 + lane];
        __nv_bfloat162 v1 = g_b2h[e1.x * 32 + lane];
        __nv_bfloat162 v2 = g_b2h[e2.x * 32 + lane];
        __nv_bfloat162 v3 = g_b2h[e3.x * 32 + lane];
        float s0 = __int_as_float(e0.y), s1 = __int_as_float(e1.y);
        float s2 = __int_as_float(e2.y), s3 = __int_as_float(e3.y);
        ax += s0 * __low2float(v0)  + s1 * __low2float(v1)
            + s2 * __low2float(v2)  + s3 * __low2float(v3);
        ay += s0 * __high2float(v0) + s1 * __high2float(v1)
            + s2 * __high2float(v2) + s3 * __high2float(v3);
    }
    for (; j < deg; ++j) {
        int2 e = es[j];
        __nv_bfloat162 v = g_b2h[e.x * 32 + lane];
        float s = __int_as_float(e.y);
        ax += s * __low2float(v);
        ay += s * __high2float(v);
    }

    // epilogue: x0 read exactly (fp32 inputs, split), b1/b2 from bf16 buffers
    const float* x0row = (w < N_USERS)
        ? (u  + (size_t)w * EMB_D)
        : (it + (size_t)(w - N_USERS) * EMB_D);
    float2 x0v = *reinterpret_cast<const float2*>(x0row + lane * 2);
    __nv_bfloat162 b1v = g_b1h[w * 32 + lane];
    __nv_bfloat162 b2v = g_b2h[w * 32 + lane];

    float2 o;
    o.x = 0.25f * (x0v.x + __low2float(b1v)  + __low2float(b2v)  + ax);
    o.y = 0.25f * (x0v.y + __high2float(b1v) + __high2float(b2v) + ay);
    *reinterpret_cast<float2*>(out + (size_t)w * EMB_D + lane * 2) = o;
}

extern "C" void kernel_launch(void* const* d_in, const int* in_sizes, int n_in,
                              void* d_out, int out_size)
{
    const float* user_emb = (const float*)d_in[0];
    const float* item_emb = (const float*)d_in[1];
    const int*   adj_row  = (const int*)  d_in[2];
    const int*   adj_col  = (const int*)  d_in[3];
    const float* adj_vals = (const float*)d_in[4];
    float*       out      = (float*)d_out;

    int* cnt;
    __nv_bfloat162 *x0h, *b1h, *b2h;
    cudaGetSymbolAddress((void**)&cnt, g_cnt);
    cudaGetSymbolAddress((void**)&x0h, g_x0h);
    cudaGetSymbolAddress((void**)&b1h, g_b1h);
    cudaGetSymbolAddress((void**)&b2h, g_b2h);

    const int T = 256;
    const int conv_blocks = (N_TOT * 16 + T - 1) / T;
    const int n4_half     = NNZ / 4 / 2;                 // 600000 quads per half
    const int scat_blocks = (n4_half + T - 1) / T;
    const int spmm_blocks = (N_TOT * 32 + T - 1) / T;    // warp per row

    cudaMemsetAsync(cnt, 0, (size_t)N_TOT * sizeof(int), 0);

    convert_kernel<<<conv_blocks, T>>>(
        (const float4*)user_emb, (const float4*)item_emb);

    // slot scatter, split into two launches (also keeps an SpMM in ncu's -s 5 window)
    scatter_kernel<<<scat_blocks, T>>>(
        (const int4*)adj_row, (const int4*)adj_col, (const float4*)adj_vals,
        0, n4_half);
    scatter_kernel<<<scat_blocks, T>>>(
        (const int4*)adj_row, (const int4*)adj_col, (const float4*)adj_vals,
        n4_half, n4_half);

    // 3 SpMM layers; layer 3 fused with the mean epilogue (b3 never materialized)
    spmm_h_kernel<<<spmm_blocks, T>>>(x0h, b1h);
    spmm_h_kernel<<<spmm_blocks, T>>>(b1h, b2h);
    spmm_final_kernel<<<spmm_blocks, T>>>(user_emb, item_emb, out);
}

// round 4
// speedup vs baseline: 1.1898x; 1.1898x over previous
#include <cuda_runtime.h>
#include <cuda_bf16.h>
#include <cstddef>

#define N_USERS 100000
#define N_ITEMS 50000
#define N_TOT   150000
#define EMB_D   64
#define NNZ     4800000
#define CAP     128            // slots per row; deg ~ Poisson(32), max over 150K rows ~ 70
#define CAPSH   7

// ---- device-global scratch (no runtime allocation allowed) ----
__device__ __align__(256) float g_b1[(size_t)N_TOT * EMB_D];
__device__ __align__(256) float g_b2[(size_t)N_TOT * EMB_D];
__device__ __align__(256) int2  g_slots[(size_t)N_TOT * CAP];   // (col, val_bits)
__device__ int g_cnt[N_TOT];

// -------- one-pass slot scatter (no scan): 4 edges/thread, vectorized --------
__global__ __launch_bounds__(256) void scatter_kernel(
    const int4* __restrict__ rows4, const int4* __restrict__ cols4,
    const float4* __restrict__ vals4, int base4, int n4)
{
    int i = blockIdx.x * blockDim.x + threadIdx.x;
    if (i >= n4) return;
    i += base4;
    int4   r = rows4[i];
    int4   c = cols4[i];
    float4 v = vals4[i];
    int p;
    p = atomicAdd(&g_cnt[r.x], 1);
    if (p < CAP) __stcs(&g_slots[((size_t)r.x << CAPSH) + p], make_int2(c.x, __float_as_int(v.x)));
    p = atomicAdd(&g_cnt[r.y], 1);
    if (p < CAP) __stcs(&g_slots[((size_t)r.y << CAPSH) + p], make_int2(c.y, __float_as_int(v.y)));
    p = atomicAdd(&g_cnt[r.z], 1);
    if (p < CAP) __stcs(&g_slots[((size_t)r.z << CAPSH) + p], make_int2(c.z, __float_as_int(v.z)));
    p = atomicAdd(&g_cnt[r.w], 1);
    if (p < CAP) __stcs(&g_slots[((size_t)r.w << CAPSH) + p], make_int2(c.w, __float_as_int(v.w)));
}

// -------- edge accumulation core: warp per row, float2 lanes, unroll 8 --------
// Slot reads use __ldcs (evict-first: streamed once, keep L1 for the x-table).
__device__ __forceinline__ float2 row_accum(
    int w, int lane, const float* __restrict__ x)
{
    int deg = g_cnt[w];
    if (deg > CAP) deg = CAP;
    const int2* es = g_slots + ((size_t)w << CAPSH);

    float ax = 0.0f, ay = 0.0f;
    int j = 0;
    for (; j + 8 <= deg; j += 8) {
        int2 e[8];
#pragma unroll
        for (int k = 0; k < 8; ++k) e[k] = __ldcs(&es[j + k]);
        float2 v[8];
#pragma unroll
        for (int k = 0; k < 8; ++k)
            v[k] = *reinterpret_cast<const float2*>(x + (size_t)e[k].x * EMB_D + lane * 2);
#pragma unroll
        for (int k = 0; k < 8; ++k) {
            float s = __int_as_float(e[k].y);
            ax += s * v[k].x;
            ay += s * v[k].y;
        }
    }
    for (; j < deg; ++j) {
        int2 e = __ldcs(&es[j]);
        float2 v = *reinterpret_cast<const float2*>(x + (size_t)e.x * EMB_D + lane * 2);
        float s = __int_as_float(e.y);
        ax += s * v.x;
        ay += s * v.y;
    }
    float2 r; r.x = ax; r.y = ay;
    return r;
}

// -------- layer 1: gather straight from the split fp32 inputs --------
__global__ __launch_bounds__(256) void spmm_l1_kernel(
    const float* __restrict__ u, const float* __restrict__ it,
    float* __restrict__ out)
{
    int w    = (blockIdx.x * blockDim.x + threadIdx.x) >> 5;
    int lane = threadIdx.x & 31;
    if (w >= N_TOT) return;

    int deg = g_cnt[w];
    if (deg > CAP) deg = CAP;
    const int2* es = g_slots + ((size_t)w << CAPSH);

    float ax = 0.0f, ay = 0.0f;
    int j = 0;
    for (; j + 4 <= deg; j += 4) {
        int2 e[4];
#pragma unroll
        for (int k = 0; k < 4; ++k) e[k] = __ldcs(&es[j + k]);
        float2 v[4];
#pragma unroll
        for (int k = 0; k < 4; ++k) {
            int c = e[k].x;
            const float* src = (c < N_USERS)
                ? (u  + (size_t)c * EMB_D)
                : (it + (size_t)(c - N_USERS) * EMB_D);
            v[k] = *reinterpret_cast<const float2*>(src + lane * 2);
        }
#pragma unroll
        for (int k = 0; k < 4; ++k) {
            float s = __int_as_float(e[k].y);
            ax += s * v[k].x;
            ay += s * v[k].y;
        }
    }
    for (; j < deg; ++j) {
        int2 e = __ldcs(&es[j]);
        int c = e.x;
        const float* src = (c < N_USERS)
            ? (u  + (size_t)c * EMB_D)
            : (it + (size_t)(c - N_USERS) * EMB_D);
        float2 v = *reinterpret_cast<const float2*>(src + lane * 2);
        float s = __int_as_float(e.y);
        ax += s * v.x;
        ay += s * v.y;
    }
    float2 o; o.x = ax; o.y = ay;
    __stcs(reinterpret_cast<float2*>(out + (size_t)w * EMB_D + lane * 2), o);
}

// -------- middle layer: contiguous fp32 in/out --------
__global__ __launch_bounds__(256) void spmm_mid_kernel(
    const float* __restrict__ x, float* __restrict__ out)
{
    int w    = (blockIdx.x * blockDim.x + threadIdx.x) >> 5;
    int lane = threadIdx.x & 31;
    if (w >= N_TOT) return;
    float2 a = row_accum(w, lane, x);
    __stcs(reinterpret_cast<float2*>(out + (size_t)w * EMB_D + lane * 2), a);
}

// -------- layer 3 + fused mean: out = 0.25*(x0 + b1 + b2 + A*b2) --------
__global__ __launch_bounds__(256) void spmm_final_kernel(
    const float* __restrict__ u, const float* __restrict__ it,
    float* __restrict__ out)
{
    int w    = (blockIdx.x * blockDim.x + threadIdx.x) >> 5;
    int lane = threadIdx.x & 31;
    if (w >= N_TOT) return;

    float2 a = row_accum(w, lane, g_b2);

    const float* x0row = (w < N_USERS)
        ? (u  + (size_t)w * EMB_D)
        : (it + (size_t)(w - N_USERS) * EMB_D);
    float2 x0 = *reinterpret_cast<const float2*>(x0row + lane * 2);
    float2 b1 = *reinterpret_cast<const float2*>(g_b1 + (size_t)w * EMB_D + lane * 2);
    float2 b2 = *reinterpret_cast<const float2*>(g_b2 + (size_t)w * EMB_D + lane * 2);

    float2 o;
    o.x = 0.25f * (x0.x + b1.x + b2.x + a.x);
    o.y = 0.25f * (x0.y + b1.y + b2.y + a.y);
    *reinterpret_cast<float2*>(out + (size_t)w * EMB_D + lane * 2) = o;
}

extern "C" void kernel_launch(void* const* d_in, const int* in_sizes, int n_in,
                              void* d_out, int out_size)
{
    const float* user_emb = (const float*)d_in[0];
    const float* item_emb = (const float*)d_in[1];
    const int*   adj_row  = (const int*)  d_in[2];
    const int*   adj_col  = (const int*)  d_in[3];
    const float* adj_vals = (const float*)d_in[4];
    float*       out      = (float*)d_out;

    int* cnt;
    float *b1, *b2;
    cudaGetSymbolAddress((void**)&cnt, g_cnt);
    cudaGetSymbolAddress((void**)&b1,  g_b1);
    cudaGetSymbolAddress((void**)&b2,  g_b2);

    const int T = 256;
    const int n4_half     = NNZ / 4 / 2;                 // 600000 quads per half
    const int scat_blocks = (n4_half + T - 1) / T;
    const int spmm_blocks = (N_TOT * 32 + T - 1) / T;    // warp per row

    cudaMemsetAsync(cnt, 0, (size_t)N_TOT * sizeof(int), 0);

    // slot scatter (two launches so ncu's -s window lands on an SpMM)
    scatter_kernel<<<scat_blocks, T>>>(
        (const int4*)adj_row, (const int4*)adj_col, (const float4*)adj_vals,
        0, n4_half);
    scatter_kernel<<<scat_blocks, T>>>(
        (const int4*)adj_row, (const int4*)adj_col, (const float4*)adj_vals,
        n4_half, n4_half);

    // 3 SpMM layers; layer 1 reads split inputs, layer 3 fused with the mean
    spmm_l1_kernel<<<spmm_blocks, T>>>(user_emb, item_emb, b1);
    spmm_mid_kernel<<<spmm_blocks, T>>>(b1, b2);
    spmm_final_kernel<<<spmm_blocks, T>>>(user_emb, item_emb, out);
}

// round 5
// speedup vs baseline: 1.3392x; 1.1255x over previous
#include <cuda_runtime.h>
#include <cuda_bf16.h>
#include <cstddef>

#define N_USERS 100000
#define N_ITEMS 50000
#define N_TOT   150000
#define EMB_D   64
#define NNZ     4800000
#define CAP     128            // slots per row; deg ~ Poisson(32), max over 150K rows ~ 70
#define CAPSH   7

// ---- device-global scratch (no runtime allocation allowed) ----
__device__ __align__(256) float g_b1[(size_t)N_TOT * EMB_D];
__device__ __align__(256) float g_b2[(size_t)N_TOT * EMB_D];
__device__ __align__(256) int2  g_slots[(size_t)N_TOT * CAP];   // (col, val_bits)
__device__ int g_cnt[N_TOT];

// -------- one-pass slot scatter (no scan): 4 edges/thread, vectorized --------
__global__ __launch_bounds__(256) void scatter_kernel(
    const int4* __restrict__ rows4, const int4* __restrict__ cols4,
    const float4* __restrict__ vals4, int base4, int n4)
{
    int i = blockIdx.x * blockDim.x + threadIdx.x;
    if (i >= n4) return;
    i += base4;
    int4   r = rows4[i];
    int4   c = cols4[i];
    float4 v = vals4[i];
    int p;
    p = atomicAdd(&g_cnt[r.x], 1);
    if (p < CAP) g_slots[((size_t)r.x << CAPSH) + p] = make_int2(c.x, __float_as_int(v.x));
    p = atomicAdd(&g_cnt[r.y], 1);
    if (p < CAP) g_slots[((size_t)r.y << CAPSH) + p] = make_int2(c.y, __float_as_int(v.y));
    p = atomicAdd(&g_cnt[r.z], 1);
    if (p < CAP) g_slots[((size_t)r.z << CAPSH) + p] = make_int2(c.z, __float_as_int(v.z));
    p = atomicAdd(&g_cnt[r.w], 1);
    if (p < CAP) g_slots[((size_t)r.w << CAPSH) + p] = make_int2(c.w, __float_as_int(v.w));
}

// -------- edge accumulation: half-warp per row, float4 lanes, unroll 4 --------
// Each warp owns 2 rows (one per half-warp) -> 2 independent gather chains and
// LDG.128 gathers (1 warp-instruction covers 2 edges / 512 B).
__device__ __forceinline__ float4 row_accum4(
    int row, int sub, const float4* __restrict__ x4)
{
    int deg = g_cnt[row];
    if (deg > CAP) deg = CAP;
    const int2* es = g_slots + ((size_t)row << CAPSH);

    float4 acc = make_float4(0.f, 0.f, 0.f, 0.f);
    int j = 0;
    for (; j + 4 <= deg; j += 4) {
        int2 e0 = es[j], e1 = es[j + 1], e2 = es[j + 2], e3 = es[j + 3];
        float4 v0 = x4[(size_t)e0.x * 16 + sub];
        float4 v1 = x4[(size_t)e1.x * 16 + sub];
        float4 v2 = x4[(size_t)e2.x * 16 + sub];
        float4 v3 = x4[(size_t)e3.x * 16 + sub];
        float s0 = __int_as_float(e0.y), s1 = __int_as_float(e1.y);
        float s2 = __int_as_float(e2.y), s3 = __int_as_float(e3.y);
        acc.x += s0 * v0.x + s1 * v1.x + s2 * v2.x + s3 * v3.x;
        acc.y += s0 * v0.y + s1 * v1.y + s2 * v2.y + s3 * v3.y;
        acc.z += s0 * v0.z + s1 * v1.z + s2 * v2.z + s3 * v3.z;
        acc.w += s0 * v0.w + s1 * v1.w + s2 * v2.w + s3 * v3.w;
    }
    for (; j < deg; ++j) {
        int2 e = es[j];
        float4 v = x4[(size_t)e.x * 16 + sub];
        float s = __int_as_float(e.y);
        acc.x += s * v.x; acc.y += s * v.y;
        acc.z += s * v.z; acc.w += s * v.w;
    }
    return acc;
}

// -------- layer 1: gather straight from the split fp32 inputs --------
__global__ __launch_bounds__(256) void spmm_l1_kernel(
    const float4* __restrict__ u4, const float4* __restrict__ it4,
    float4* __restrict__ out4)
{
    int t    = blockIdx.x * blockDim.x + threadIdx.x;
    int row  = (t >> 4);                 // 2 rows per warp, one per half-warp
    int sub  = t & 15;
    if (row >= N_TOT) return;

    int deg = g_cnt[row];
    if (deg > CAP) deg = CAP;
    const int2* es = g_slots + ((size_t)row << CAPSH);

    float4 acc = make_float4(0.f, 0.f, 0.f, 0.f);
    int j = 0;
    for (; j + 4 <= deg; j += 4) {
        int2 e[4];
#pragma unroll
        for (int k = 0; k < 4; ++k) e[k] = es[j + k];
        float4 v[4];
#pragma unroll
        for (int k = 0; k < 4; ++k) {
            int c = e[k].x;
            v[k] = (c < N_USERS)
                ? u4[(size_t)c * 16 + sub]
                : it4[(size_t)(c - N_USERS) * 16 + sub];
        }
#pragma unroll
        for (int k = 0; k < 4; ++k) {
            float s = __int_as_float(e[k].y);
            acc.x += s * v[k].x; acc.y += s * v[k].y;
            acc.z += s * v[k].z; acc.w += s * v[k].w;
        }
    }
    for (; j < deg; ++j) {
        int2 e = es[j];
        int c = e.x;
        float4 v = (c < N_USERS)
            ? u4[(size_t)c * 16 + sub]
            : it4[(size_t)(c - N_USERS) * 16 + sub];
        float s = __int_as_float(e.y);
        acc.x += s * v.x; acc.y += s * v.y;
        acc.z += s * v.z; acc.w += s * v.w;
    }
    out4[(size_t)row * 16 + sub] = acc;
}

// -------- middle layer: contiguous fp32 in/out --------
__global__ __launch_bounds__(256) void spmm_mid_kernel(
    const float4* __restrict__ x4, float4* __restrict__ out4)
{
    int t   = blockIdx.x * blockDim.x + threadIdx.x;
    int row = t >> 4;
    int sub = t & 15;
    if (row >= N_TOT) return;
    out4[(size_t)row * 16 + sub] = row_accum4(row, sub, x4);
}

// -------- layer 3 + fused mean: out = 0.25*(x0 + b1 + b2 + A*b2) --------
__global__ __launch_bounds__(256) void spmm_final_kernel(
    const float4* __restrict__ u4, const float4* __restrict__ it4,
    float4* __restrict__ out4)
{
    int t   = blockIdx.x * blockDim.x + threadIdx.x;
    int row = t >> 4;
    int sub = t & 15;
    if (row >= N_TOT) return;

    float4 a = row_accum4(row, sub, (const float4*)g_b2);

    float4 x0 = (row < N_USERS)
        ? u4[(size_t)row * 16 + sub]
        : it4[(size_t)(row - N_USERS) * 16 + sub];
    float4 b1 = reinterpret_cast<const float4*>(g_b1)[(size_t)row * 16 + sub];
    float4 b2 = reinterpret_cast<const float4*>(g_b2)[(size_t)row * 16 + sub];

    float4 o;
    o.x = 0.25f * (x0.x + b1.x + b2.x + a.x);
    o.y = 0.25f * (x0.y + b1.y + b2.y + a.y);
    o.z = 0.25f * (x0.z + b1.z + b2.z + a.z);
    o.w = 0.25f * (x0.w + b1.w + b2.w + a.w);
    out4[(size_t)row * 16 + sub] = o;
}

extern "C" void kernel_launch(void* const* d_in, const int* in_sizes, int n_in,
                              void* d_out, int out_size)
{
    const float* user_emb = (const float*)d_in[0];
    const float* item_emb = (const float*)d_in[1];
    const int*   adj_row  = (const int*)  d_in[2];
    const int*   adj_col  = (const int*)  d_in[3];
    const float* adj_vals = (const float*)d_in[4];
    float*       out      = (float*)d_out;

    int* cnt;
    float *b1;
    cudaGetSymbolAddress((void**)&cnt, g_cnt);
    cudaGetSymbolAddress((void**)&b1,  g_b1);
    float* b2;
    cudaGetSymbolAddress((void**)&b2,  g_b2);

    const int T = 256;
    const int n4_half     = NNZ / 4 / 2;                  // 600000 quads per half
    const int scat_blocks = (n4_half + T - 1) / T;
    const int spmm_blocks = (N_TOT * 16 + T - 1) / T;     // 16 threads per row

    cudaMemsetAsync(cnt, 0, (size_t)N_TOT * sizeof(int), 0);

    // slot scatter (two launches so ncu's -s window lands on an SpMM)
    scatter_kernel<<<scat_blocks, T>>>(
        (const int4*)adj_row, (const int4*)adj_col, (const float4*)adj_vals,
        0, n4_half);
    scatter_kernel<<<scat_blocks, T>>>(
        (const int4*)adj_row, (const int4*)adj_col, (const float4*)adj_vals,
        n4_half, n4_half);

    // 3 SpMM layers; layer 1 reads split inputs, layer 3 fused with the mean
    spmm_l1_kernel<<<spmm_blocks, T>>>(
        (const float4*)user_emb, (const float4*)item_emb, (float4*)b1);
    spmm_mid_kernel<<<spmm_blocks, T>>>((const float4*)b1, (float4*)b2);
    spmm_final_kernel<<<spmm_blocks, T>>>(
        (const float4*)user_emb, (const float4*)item_emb, (float4*)out);
}